// round 9
// baseline (speedup 1.0000x reference)
#include <cuda_runtime.h>
#include <cstdint>

#define S_LEN 8192
#define DIM   256
#define HID2  256
#define NTAG  16
#define NEGV  (-10000.0f)
typedef unsigned long long ull;

__device__ float g_pre[2u * S_LEN * 1024];
__device__ float g_hs [S_LEN * 512];
__device__ float g_feats[S_LEN * NTAG];
__device__ unsigned char g_back[S_LEN * NTAG];

__device__ __forceinline__ void fma2(ull &d, ull a, ull b) {
    asm("fma.rn.f32x2 %0, %1, %2, %0;" : "+l"(d) : "l"(a), "l"(b));
}
__device__ __forceinline__ unsigned s2u(const void* p) {
    unsigned a;
    asm("{ .reg .u64 t; cvta.to.shared.u64 t, %1; cvt.u32.u64 %0, t; }" : "=r"(a) : "l"(p));
    return a;
}
__device__ __forceinline__ unsigned mapa_(unsigned la, unsigned rk) {
    unsigned r;
    asm("mapa.shared::cluster.u32 %0, %1, %2;" : "=r"(r) : "r"(la), "r"(rk));
    return r;
}
__device__ __forceinline__ void cluster_sync_() {
    asm volatile("barrier.cluster.arrive.aligned;" ::: "memory");
    asm volatile("barrier.cluster.wait.aligned;"   ::: "memory");
}
__device__ __forceinline__ float sigm(float x) { return __fdividef(1.0f, 1.0f + __expf(-x)); }
__device__ __forceinline__ float tanh_(float x) { return __fdividef(2.0f, 1.0f + __expf(-2.0f * x)) - 1.0f; }

#define WAIT_ACQ(maddr, par) do {                                             \
    asm volatile("{\n\t.reg .pred P;\n\tWL_%=:\n\t"                           \
        "mbarrier.try_wait.parity.acquire.cluster.shared::cta.b64 P, [%0], %1, 0x989680;\n\t" \
        "@P bra WD_%=;\n\tbra WL_%=;\n\tWD_%=:\n\t}"                          \
        :: "r"(maddr), "r"(par) : "memory");                                  \
} while (0)

// ========================= K1: input projections ============================
__global__ __launch_bounds__(256) void k_pre(
    const int* __restrict__ sent, const float* __restrict__ emb,
    const float* __restrict__ w_ih_f, const float* __restrict__ b_f,
    const float* __restrict__ w_ih_b, const float* __restrict__ b_b)
{
    __shared__ float4 xs4[16 * 64];
    const int dir = blockIdx.y, t0 = blockIdx.x * 16, tid = threadIdx.x;
    const float* w    = dir ? w_ih_b : w_ih_f;
    const float* bias = dir ? b_b    : b_f;
    {
        int r = tid >> 4, seg = tid & 15;
        int tsrc = dir ? (S_LEN - 1 - (t0 + r)) : (t0 + r);
        int tok  = __ldg(&sent[tsrc]);
        const float4* er = (const float4*)(emb + (size_t)tok * DIM);
#pragma unroll
        for (int ii = 0; ii < 4; ii++) xs4[r * 64 + seg + 16 * ii] = __ldg(&er[seg + 16 * ii]);
    }
    __syncthreads();
    const int m = tid;
    for (int q = 0; q < 4; q++) {
        const float4* wr = (const float4*)(w + (size_t)(q * HID2 + m) * DIM);
        float acc[16];
#pragma unroll
        for (int tt = 0; tt < 16; tt++) acc[tt] = 0.0f;
        for (int k4 = 0; k4 < 64; k4++) {
            float4 w4 = __ldg(&wr[k4]);
#pragma unroll
            for (int tt = 0; tt < 16; tt++) {
                float4 x4 = xs4[tt * 64 + k4];
                acc[tt] += w4.x * x4.x + w4.y * x4.y + w4.z * x4.z + w4.w * x4.w;
            }
        }
        float bq = __ldg(&bias[q * HID2 + m]);
        size_t base = ((size_t)dir * S_LEN + t0) * 1024 + (size_t)m * 4 + q;
#pragma unroll
        for (int tt = 0; tt < 16; tt++) g_pre[base + (size_t)tt * 1024] = acc[tt] + bq;
    }
}

// == K2a: LSTM, 16-CTA cluster x 128 thr, per-warp flags, same-thread release =
__global__ void __launch_bounds__(128, 1)
k_lstm16(const float* __restrict__ w_hh_f, const float* __restrict__ w_hh_b,
         const float* __restrict__ h0_f, const float* __restrict__ c0_f,
         const float* __restrict__ h0_b, const float* __restrict__ c0_b)
{
    __shared__ float h_sm[2][HID2];
    __shared__ int flg[64];                       // [src_rank*4 + src_warp]
    const int tid  = threadIdx.x;
    const int rank = blockIdx.x & 15, dir = blockIdx.x >> 4;
    const int w = tid >> 5, lane = tid & 31, u = lane >> 3, s = lane & 7;
    const int m = rank * 16 + w * 4 + u;

    const float* w_hh = dir ? w_hh_b : w_hh_f;
    const float* h0   = dir ? h0_b : h0_f;
    const float* c0   = dir ? c0_b : c0_f;

    ull wv[4][16];
#pragma unroll
    for (int g = 0; g < 4; g++) {
        const ull* row = (const ull*)(w_hh + (size_t)(g * HID2 + m) * HID2);
#pragma unroll
        for (int q = 0; q < 16; q++) wv[g][q] = __ldg(&row[s + 8 * q]);
    }

    if (tid < 64) flg[tid] = 0;
    h_sm[0][tid] = h0[tid];
    h_sm[0][tid + 128] = h0[tid + 128];
    float c = c0[m];
    __syncthreads();
    cluster_sync_();

    const unsigned flga = s2u(&flg[0]);
    unsigned fpost = 0, da0 = 0, da1 = 0;
    if (lane < 16) {
        da0 = mapa_(s2u(&h_sm[0][rank * 16 + w * 4]), (unsigned)lane);
        da1 = mapa_(s2u(&h_sm[1][rank * 16 + w * 4]), (unsigned)lane);
        fpost = mapa_(s2u(&flg[rank * 4 + w]), (unsigned)lane);
    }

    const float4* prep = (const float4*)(g_pre + (size_t)dir * S_LEN * 1024) + m;
    float4 pre_cur = __ldg(&prep[0]);
    float* hs_base = g_hs + dir * HID2 + rank * 16 + w * 4;

    for (int t = 0; t < S_LEN; t++) {
        int tn = (t + 1 < S_LEN) ? t + 1 : t;
        float4 pre_next = __ldg(&prep[(size_t)tn * 256]);

        // wait: all 16 CTAs x 4 warps have posted step t (2 flags per lane)
        for (;;) {
            int v0, v1;
            asm volatile("ld.acquire.cluster.shared::cta.b32 %0, [%1];"
                         : "=r"(v0) : "r"(flga + 8u * (unsigned)lane));
            asm volatile("ld.acquire.cluster.shared::cta.b32 %0, [%1];"
                         : "=r"(v1) : "r"(flga + 8u * (unsigned)lane + 4u));
            if (__all_sync(0xffffffffu, (v0 >= t) & (v1 >= t))) break;
        }

        ull a0 = 0, a1 = 0, a2 = 0, a3 = 0;
        const ull* hp = (const ull*)&h_sm[t & 1][0];
#pragma unroll
        for (int q = 0; q < 16; q++) {
            ull h2 = hp[s + 8 * q];
            fma2(a0, wv[0][q], h2); fma2(a1, wv[1][q], h2);
            fma2(a2, wv[2][q], h2); fma2(a3, wv[3][q], h2);
        }
        float2 f0 = *(float2*)&a0, f1 = *(float2*)&a1, f2 = *(float2*)&a2, f3 = *(float2*)&a3;
        float s0 = f0.x + f0.y, s1 = f1.x + f1.y, s2 = f2.x + f2.y, s3 = f3.x + f3.y;
#pragma unroll
        for (int msk = 1; msk < 8; msk <<= 1) {
            s0 += __shfl_xor_sync(0xffffffffu, s0, msk);
            s1 += __shfl_xor_sync(0xffffffffu, s1, msk);
            s2 += __shfl_xor_sync(0xffffffffu, s2, msk);
            s3 += __shfl_xor_sync(0xffffffffu, s3, msk);
        }
        float gi = sigm(pre_cur.x + s0), gf = sigm(pre_cur.y + s1);
        float gg = tanh_(pre_cur.z + s2), go = sigm(pre_cur.w + s3);
        c = gf * c + gi * gg;
        float h = go * tanh_(c);

        float p0 = __shfl_sync(0xffffffffu, h, s);
        float p1 = __shfl_sync(0xffffffffu, h, s + 8);
        float p2 = __shfl_sync(0xffffffffu, h, s + 16);
        float p3 = __shfl_sync(0xffffffffu, h, s + 24);
        if (lane < 16) {
            unsigned da = (t & 1) ? da0 : da1;    // write buf[(t+1)&1]
            asm volatile("st.shared::cluster.v4.f32 [%0], {%1,%2,%3,%4};"
                         :: "r"(da), "f"(p0), "f"(p1), "f"(p2), "f"(p3) : "memory");
            asm volatile("st.release.cluster.shared::cluster.b32 [%0], %1;"
                         :: "r"(fpost), "r"(t + 1) : "memory");
        }
        if (lane == 0) {
            int tpos = dir ? (S_LEN - 1 - t) : t;
            *(float4*)(hs_base + (size_t)tpos * 512) = make_float4(p0, p1, p2, p3);
        }
        pre_cur = pre_next;
    }
    cluster_sync_();
}

// ====== K2b fallback: proven 8-CTA mbarrier version (R6, 12087us) ===========
__global__ void __cluster_dims__(8, 1, 1) __launch_bounds__(256, 1)
k_lstm8(const float* __restrict__ w_hh_f, const float* __restrict__ w_hh_b,
        const float* __restrict__ h0_f, const float* __restrict__ c0_f,
        const float* __restrict__ h0_b, const float* __restrict__ c0_b)
{
    __shared__ float h_sm[3][HID2];
    __shared__ ull mb[3];
    const int tid  = threadIdx.x;
    const int rank = blockIdx.x & 7, dir = blockIdx.x >> 3;
    const int w = tid >> 5, lane = tid & 31, u = lane >> 3, s = lane & 7;
    const int m = rank * 32 + w * 4 + u;

    const float* w_hh = dir ? w_hh_b : w_hh_f;
    const float* h0   = dir ? h0_b : h0_f;
    const float* c0   = dir ? c0_b : c0_f;

    ull wv[4][16];
#pragma unroll
    for (int g = 0; g < 4; g++) {
        const ull* row = (const ull*)(w_hh + (size_t)(g * HID2 + m) * HID2);
#pragma unroll
        for (int q = 0; q < 16; q++) wv[g][q] = __ldg(&row[s + 8 * q]);
    }

    if (tid < 3) {
        unsigned ma = s2u(&mb[tid]);
        asm volatile("mbarrier.init.shared.b64 [%0], 64;" :: "r"(ma) : "memory");
    }
    if (tid < HID2) h_sm[0][tid] = h0[tid];
    float c = c0[m];
    __syncthreads();
    cluster_sync_();

    unsigned mba[3]  = { s2u(&mb[0]), s2u(&mb[1]), s2u(&mb[2]) };
    unsigned dsta[3] = { s2u(&h_sm[0][rank * 32 + w * 4]),
                         s2u(&h_sm[1][rank * 32 + w * 4]),
                         s2u(&h_sm[2][rank * 32 + w * 4]) };

    const float4* prep = (const float4*)(g_pre + (size_t)dir * S_LEN * 1024) + m;
    float4 pre_cur = __ldg(&prep[0]);
    float* hs_out = g_hs + dir * HID2 + m;

    auto STEP = [&](int t, int b, int dowait, int parity) {
        int tn = (t + 1 < S_LEN) ? t + 1 : t;
        float4 pre_next = __ldg(&prep[(size_t)tn * 256]);
        if (dowait) WAIT_ACQ(mba[b], parity);
        ull a0 = 0, a1 = 0, a2 = 0, a3 = 0;
        const ull* hp = (const ull*)&h_sm[b][0];
#pragma unroll
        for (int q = 0; q < 16; q++) {
            ull h2 = hp[s + 8 * q];
            fma2(a0, wv[0][q], h2); fma2(a1, wv[1][q], h2);
            fma2(a2, wv[2][q], h2); fma2(a3, wv[3][q], h2);
        }
        float2 f0 = *(float2*)&a0, f1 = *(float2*)&a1, f2 = *(float2*)&a2, f3 = *(float2*)&a3;
        float s0 = f0.x + f0.y, s1 = f1.x + f1.y, s2 = f2.x + f2.y, s3 = f3.x + f3.y;
#pragma unroll
        for (int msk = 1; msk < 8; msk <<= 1) {
            s0 += __shfl_xor_sync(0xffffffffu, s0, msk);
            s1 += __shfl_xor_sync(0xffffffffu, s1, msk);
            s2 += __shfl_xor_sync(0xffffffffu, s2, msk);
            s3 += __shfl_xor_sync(0xffffffffu, s3, msk);
        }
        float gi = sigm(pre_cur.x + s0), gf = sigm(pre_cur.y + s1);
        float gg = tanh_(pre_cur.z + s2), go = sigm(pre_cur.w + s3);
        c = gf * c + gi * gg;
        float h = go * tanh_(c);

        int bn = (b + 1) % 3;
        float p0 = __shfl_sync(0xffffffffu, h, s);
        float p1 = __shfl_sync(0xffffffffu, h, s + 8);
        float p2 = __shfl_sync(0xffffffffu, h, s + 16);
        float p3 = __shfl_sync(0xffffffffu, h, s + 24);
        if (lane < 8) {
            unsigned da = mapa_(dsta[bn], (unsigned)lane);
            asm volatile("st.shared::cluster.v4.f32 [%0], {%1,%2,%3,%4};"
                         :: "r"(da), "f"(p0), "f"(p1), "f"(p2), "f"(p3) : "memory");
            unsigned ba = mapa_(mba[bn], (unsigned)lane);
            asm volatile("mbarrier.arrive.release.cluster.shared::cluster.b64 _, [%0];"
                         :: "r"(ba) : "memory");
        }
        if (s == 0) {
            int tpos = dir ? (S_LEN - 1 - t) : t;
            hs_out[(size_t)tpos * 512] = h;
        }
        pre_cur = pre_next;
    };

    STEP(0, 0, 0, 0);
    int par = 0;
    for (int t = 1; t < S_LEN - 1; t += 3) {
        STEP(t,     1, 1, par);
        STEP(t + 1, 2, 1, par);
        STEP(t + 2, 0, 1, par);
        par ^= 1;
    }
    STEP(S_LEN - 1, 1, 1, par);
    cluster_sync_();
}

// ========================= K3: output projection ============================
__global__ __launch_bounds__(128) void k_feats(
    const float* __restrict__ w_out, const float* __restrict__ b_out)
{
    __shared__ float w_sm[NTAG * 516];
    const int tid = threadIdx.x;
    for (int idx = tid; idx < NTAG * 512; idx += 128)
        w_sm[(idx >> 9) * 516 + (idx & 511)] = __ldg(&w_out[idx]);
    __syncthreads();
    const int tl = tid >> 4, tag = tid & 15;
    const int t = blockIdx.x * 8 + tl;
    const float4* hp = (const float4*)(g_hs + (size_t)t * 512);
    const float4* wp = (const float4*)(w_sm + tag * 516);
    float acc = 0.0f;
#pragma unroll 4
    for (int k4 = 0; k4 < 128; k4++) {
        float4 h4 = hp[k4], w4 = wp[k4];
        acc += h4.x * w4.x + h4.y * w4.y + h4.z * w4.z + h4.w * w4.w;
    }
    g_feats[t * NTAG + tag] = acc + __ldg(&b_out[tag]);
}

// ========================= K4: Viterbi ======================================
__global__ __launch_bounds__(32) void k_vit(
    const float* __restrict__ trans, float* __restrict__ out, int out_size)
{
    __shared__ float fin_sm[NTAG];
    const int tid = threadIdx.x, j = tid & 15;
    float tr[NTAG];
#pragma unroll
    for (int i = 0; i < NTAG; i++) tr[i] = __ldg(&trans[j * NTAG + i]);

    float score = (j == 0) ? 0.0f : NEGV;
    float fcur = g_feats[j];
    for (int t = 0; t < S_LEN; t++) {
        float fnext = (t + 1 < S_LEN) ? g_feats[(t + 1) * NTAG + j] : 0.0f;
        float best = -3.4e38f; int bi = 0;
#pragma unroll
        for (int i = 0; i < NTAG; i++) {
            float si = __shfl_sync(0xffffffffu, score, i);
            float cand = si + tr[i];
            if (cand > best) { best = cand; bi = i; }
        }
        if (tid < NTAG) g_back[t * NTAG + j] = (unsigned char)bi;
        score = best + fcur;
        fcur = fnext;
    }
    if (tid < NTAG) fin_sm[j] = score + __ldg(&trans[1 * NTAG + j]);
    __syncwarp();
    if (tid == 0) {
        float bs = fin_sm[0]; int bl = 0;
#pragma unroll
        for (int i = 1; i < NTAG; i++) if (fin_sm[i] > bs) { bs = fin_sm[i]; bl = i; }
        const int off = (out_size > S_LEN) ? 1 : 0;
        if (off) out[0] = bs;
        int tag = bl;
#pragma unroll 4
        for (int t = S_LEN - 1; t > 0; t--) {
            out[off + t] = (float)tag;
            uint4 row = *(const uint4*)&g_back[t * NTAG];
            unsigned wsel = (tag & 8) ? ((tag & 4) ? row.w : row.z)
                                      : ((tag & 4) ? row.y : row.x);
            tag = (int)((wsel >> (8 * (tag & 3))) & 0xFu);
        }
        out[off] = (float)tag;
    }
}

extern "C" void kernel_launch(void* const* d_in, const int* in_sizes, int n_in,
                              void* d_out, int out_size)
{
    (void)in_sizes; (void)n_in;
    const int*   sent   = (const int*)  d_in[0];
    const float* emb    = (const float*)d_in[1];
    const float* w_ih_f = (const float*)d_in[2];
    const float* w_hh_f = (const float*)d_in[3];
    const float* b_f    = (const float*)d_in[4];
    const float* w_ih_b = (const float*)d_in[5];
    const float* w_hh_b = (const float*)d_in[6];
    const float* b_b    = (const float*)d_in[7];
    const float* h0_f   = (const float*)d_in[8];
    const float* c0_f   = (const float*)d_in[9];
    const float* h0_b   = (const float*)d_in[10];
    const float* c0_b   = (const float*)d_in[11];
    const float* w_out  = (const float*)d_in[12];
    const float* b_out  = (const float*)d_in[13];
    const float* trans  = (const float*)d_in[14];

    k_pre<<<dim3(512, 2), 256>>>(sent, emb, w_ih_f, b_f, w_ih_b, b_b);

    // Unconditionally try the 16-CTA non-portable cluster launch; the driver
    // rejects it synchronously if unsupported, in which case fall back.
    bool ok16 = false;
    cudaFuncSetAttribute((const void*)k_lstm16,
                         cudaFuncAttributeNonPortableClusterSizeAllowed, 1);
    {
        cudaLaunchConfig_t cfg = {};
        cfg.gridDim = dim3(32, 1, 1);
        cfg.blockDim = dim3(128, 1, 1);
        cfg.dynamicSmemBytes = 0;
        cfg.stream = 0;
        cudaLaunchAttribute at[1];
        at[0].id = cudaLaunchAttributeClusterDimension;
        at[0].val.clusterDim.x = 16;
        at[0].val.clusterDim.y = 1;
        at[0].val.clusterDim.z = 1;
        cfg.attrs = at;
        cfg.numAttrs = 1;
        if (cudaLaunchKernelEx(&cfg, k_lstm16,
                               w_hh_f, w_hh_b, h0_f, c0_f, h0_b, c0_b) == cudaSuccess)
            ok16 = true;
    }
    if (!ok16)
        k_lstm8<<<16, 256>>>(w_hh_f, w_hh_b, h0_f, c0_f, h0_b, c0_b);

    k_feats<<<1024, 128>>>(w_out, b_out);
    k_vit<<<1, 32>>>(trans, (float*)d_out, out_size);
}

// round 10
// speedup vs baseline: 1.1354x; 1.1354x over previous
#include <cuda_runtime.h>
#include <cstdint>
#include <cstdio>

#define S_LEN 8192
#define DIM   256
#define HID2  256
#define NTAG  16
#define NEGV  (-10000.0f)
typedef unsigned long long ull;

__device__ float g_pre[2u * S_LEN * 1024];
__device__ float g_hs [S_LEN * 512];
__device__ float g_feats[S_LEN * NTAG];
__device__ unsigned char g_back[S_LEN * NTAG];

__device__ __forceinline__ void fma2(ull &d, ull a, ull b) {
    asm("fma.rn.f32x2 %0, %1, %2, %0;" : "+l"(d) : "l"(a), "l"(b));
}
__device__ __forceinline__ unsigned s2u(const void* p) {
    unsigned a;
    asm("{ .reg .u64 t; cvta.to.shared.u64 t, %1; cvt.u32.u64 %0, t; }" : "=r"(a) : "l"(p));
    return a;
}
__device__ __forceinline__ unsigned mapa_(unsigned la, unsigned rk) {
    unsigned r;
    asm("mapa.shared::cluster.u32 %0, %1, %2;" : "=r"(r) : "r"(la), "r"(rk));
    return r;
}
__device__ __forceinline__ void cluster_sync_() {
    asm volatile("barrier.cluster.arrive.aligned;" ::: "memory");
    asm volatile("barrier.cluster.wait.aligned;"   ::: "memory");
}
__device__ __forceinline__ float sigm(float x) { return __fdividef(1.0f, 1.0f + __expf(-x)); }
__device__ __forceinline__ float tanh_(float x) { return __fdividef(2.0f, 1.0f + __expf(-2.0f * x)) - 1.0f; }

#define WAIT_ACQ(maddr, par) do {                                             \
    asm volatile("{\n\t.reg .pred P;\n\tWL_%=:\n\t"                           \
        "mbarrier.try_wait.parity.acquire.cluster.shared::cta.b64 P, [%0], %1, 0x989680;\n\t" \
        "@P bra WD_%=;\n\tbra WL_%=;\n\tWD_%=:\n\t}"                          \
        :: "r"(maddr), "r"(par) : "memory");                                  \
} while (0)

// ========================= K1: input projections ============================
__global__ __launch_bounds__(256) void k_pre(
    const int* __restrict__ sent, const float* __restrict__ emb,
    const float* __restrict__ w_ih_f, const float* __restrict__ b_f,
    const float* __restrict__ w_ih_b, const float* __restrict__ b_b)
{
    long long t_start = 0;
    if (blockIdx.x == 0 && blockIdx.y == 0 && threadIdx.x == 0) t_start = clock64();
    __shared__ float4 xs4[16 * 64];
    const int dir = blockIdx.y, t0 = blockIdx.x * 16, tid = threadIdx.x;
    const float* w    = dir ? w_ih_b : w_ih_f;
    const float* bias = dir ? b_b    : b_f;
    {
        int r = tid >> 4, seg = tid & 15;
        int tsrc = dir ? (S_LEN - 1 - (t0 + r)) : (t0 + r);
        int tok  = __ldg(&sent[tsrc]);
        const float4* er = (const float4*)(emb + (size_t)tok * DIM);
#pragma unroll
        for (int ii = 0; ii < 4; ii++) xs4[r * 64 + seg + 16 * ii] = __ldg(&er[seg + 16 * ii]);
    }
    __syncthreads();
    const int m = tid;
    for (int q = 0; q < 4; q++) {
        const float4* wr = (const float4*)(w + (size_t)(q * HID2 + m) * DIM);
        float acc[16];
#pragma unroll
        for (int tt = 0; tt < 16; tt++) acc[tt] = 0.0f;
        for (int k4 = 0; k4 < 64; k4++) {
            float4 w4 = __ldg(&wr[k4]);
#pragma unroll
            for (int tt = 0; tt < 16; tt++) {
                float4 x4 = xs4[tt * 64 + k4];
                acc[tt] += w4.x * x4.x + w4.y * x4.y + w4.z * x4.z + w4.w * x4.w;
            }
        }
        float bq = __ldg(&bias[q * HID2 + m]);
        size_t base = ((size_t)dir * S_LEN + t0) * 1024 + (size_t)m * 4 + q;
#pragma unroll
        for (int tt = 0; tt < 16; tt++) g_pre[base + (size_t)tt * 1024] = acc[tt] + bq;
    }
    if (blockIdx.x == 0 && blockIdx.y == 0 && threadIdx.x == 0)
        printf("DIAG k_pre block0 cycles=%lld\n", clock64() - t_start);
}

// == K2a: LSTM, 16-CTA cluster x 128 thr, per-warp flags, same-thread release =
__global__ void __launch_bounds__(128, 1)
k_lstm16(const float* __restrict__ w_hh_f, const float* __restrict__ w_hh_b,
         const float* __restrict__ h0_f, const float* __restrict__ c0_f,
         const float* __restrict__ h0_b, const float* __restrict__ c0_b)
{
    __shared__ float h_sm[2][HID2];
    __shared__ int flg[64];
    const int tid  = threadIdx.x;
    const int rank = blockIdx.x & 15, dir = blockIdx.x >> 4;
    const int w = tid >> 5, lane = tid & 31, u = lane >> 3, s = lane & 7;
    const int m = rank * 16 + w * 4 + u;

    const float* w_hh = dir ? w_hh_b : w_hh_f;
    const float* h0   = dir ? h0_b : h0_f;
    const float* c0   = dir ? c0_b : c0_f;

    ull wv[4][16];
#pragma unroll
    for (int g = 0; g < 4; g++) {
        const ull* row = (const ull*)(w_hh + (size_t)(g * HID2 + m) * HID2);
#pragma unroll
        for (int q = 0; q < 16; q++) wv[g][q] = __ldg(&row[s + 8 * q]);
    }

    if (tid < 64) flg[tid] = 0;
    h_sm[0][tid] = h0[tid];
    h_sm[0][tid + 128] = h0[tid + 128];
    float c = c0[m];
    __syncthreads();
    cluster_sync_();

    long long t_start = 0;
    if (blockIdx.x == 0 && tid == 0) t_start = clock64();

    const unsigned flga = s2u(&flg[0]);
    unsigned fpost = 0, da0 = 0, da1 = 0;
    if (lane < 16) {
        da0 = mapa_(s2u(&h_sm[0][rank * 16 + w * 4]), (unsigned)lane);
        da1 = mapa_(s2u(&h_sm[1][rank * 16 + w * 4]), (unsigned)lane);
        fpost = mapa_(s2u(&flg[rank * 4 + w]), (unsigned)lane);
    }

    const float4* prep = (const float4*)(g_pre + (size_t)dir * S_LEN * 1024) + m;
    float4 pre_cur = __ldg(&prep[0]);
    float* hs_base = g_hs + dir * HID2 + rank * 16 + w * 4;

    for (int t = 0; t < S_LEN; t++) {
        int tn = (t + 1 < S_LEN) ? t + 1 : t;
        float4 pre_next = __ldg(&prep[(size_t)tn * 256]);

        for (;;) {
            int v0, v1;
            asm volatile("ld.acquire.cluster.shared::cta.b32 %0, [%1];"
                         : "=r"(v0) : "r"(flga + 8u * (unsigned)lane));
            asm volatile("ld.acquire.cluster.shared::cta.b32 %0, [%1];"
                         : "=r"(v1) : "r"(flga + 8u * (unsigned)lane + 4u));
            if (__all_sync(0xffffffffu, (v0 >= t) & (v1 >= t))) break;
        }

        ull a0 = 0, a1 = 0, a2 = 0, a3 = 0;
        const ull* hp = (const ull*)&h_sm[t & 1][0];
#pragma unroll
        for (int q = 0; q < 16; q++) {
            ull h2 = hp[s + 8 * q];
            fma2(a0, wv[0][q], h2); fma2(a1, wv[1][q], h2);
            fma2(a2, wv[2][q], h2); fma2(a3, wv[3][q], h2);
        }
        float2 f0 = *(float2*)&a0, f1 = *(float2*)&a1, f2 = *(float2*)&a2, f3 = *(float2*)&a3;
        float s0 = f0.x + f0.y, s1 = f1.x + f1.y, s2 = f2.x + f2.y, s3 = f3.x + f3.y;
#pragma unroll
        for (int msk = 1; msk < 8; msk <<= 1) {
            s0 += __shfl_xor_sync(0xffffffffu, s0, msk);
            s1 += __shfl_xor_sync(0xffffffffu, s1, msk);
            s2 += __shfl_xor_sync(0xffffffffu, s2, msk);
            s3 += __shfl_xor_sync(0xffffffffu, s3, msk);
        }
        float gi = sigm(pre_cur.x + s0), gf = sigm(pre_cur.y + s1);
        float gg = tanh_(pre_cur.z + s2), go = sigm(pre_cur.w + s3);
        c = gf * c + gi * gg;
        float h = go * tanh_(c);

        float p0 = __shfl_sync(0xffffffffu, h, s);
        float p1 = __shfl_sync(0xffffffffu, h, s + 8);
        float p2 = __shfl_sync(0xffffffffu, h, s + 16);
        float p3 = __shfl_sync(0xffffffffu, h, s + 24);
        if (lane < 16) {
            unsigned da = (t & 1) ? da0 : da1;
            asm volatile("st.shared::cluster.v4.f32 [%0], {%1,%2,%3,%4};"
                         :: "r"(da), "f"(p0), "f"(p1), "f"(p2), "f"(p3) : "memory");
            asm volatile("st.release.cluster.shared::cluster.b32 [%0], %1;"
                         :: "r"(fpost), "r"(t + 1) : "memory");
        }
        if (lane == 0) {
            int tpos = dir ? (S_LEN - 1 - t) : t;
            *(float4*)(hs_base + (size_t)tpos * 512) = make_float4(p0, p1, p2, p3);
        }
        pre_cur = pre_next;
    }
    if (blockIdx.x == 0 && tid == 0) {
        long long dt = clock64() - t_start;
        printf("DIAG k_lstm16 cycles=%lld per_step=%lld\n", dt, dt / S_LEN);
    }
    cluster_sync_();
}

// ====== K2b fallback: proven 8-CTA mbarrier version (R6, 12087us) ===========
__global__ void __cluster_dims__(8, 1, 1) __launch_bounds__(256, 1)
k_lstm8(const float* __restrict__ w_hh_f, const float* __restrict__ w_hh_b,
        const float* __restrict__ h0_f, const float* __restrict__ c0_f,
        const float* __restrict__ h0_b, const float* __restrict__ c0_b)
{
    __shared__ float h_sm[3][HID2];
    __shared__ ull mb[3];
    const int tid  = threadIdx.x;
    const int rank = blockIdx.x & 7, dir = blockIdx.x >> 3;
    const int w = tid >> 5, lane = tid & 31, u = lane >> 3, s = lane & 7;
    const int m = rank * 32 + w * 4 + u;

    const float* w_hh = dir ? w_hh_b : w_hh_f;
    const float* h0   = dir ? h0_b : h0_f;
    const float* c0   = dir ? c0_b : c0_f;

    ull wv[4][16];
#pragma unroll
    for (int g = 0; g < 4; g++) {
        const ull* row = (const ull*)(w_hh + (size_t)(g * HID2 + m) * HID2);
#pragma unroll
        for (int q = 0; q < 16; q++) wv[g][q] = __ldg(&row[s + 8 * q]);
    }

    if (tid < 3) {
        unsigned ma = s2u(&mb[tid]);
        asm volatile("mbarrier.init.shared.b64 [%0], 64;" :: "r"(ma) : "memory");
    }
    if (tid < HID2) h_sm[0][tid] = h0[tid];
    float c = c0[m];
    __syncthreads();
    cluster_sync_();

    long long t_start = 0;
    if (blockIdx.x == 0 && tid == 0) t_start = clock64();

    unsigned mba[3]  = { s2u(&mb[0]), s2u(&mb[1]), s2u(&mb[2]) };
    unsigned dsta[3] = { s2u(&h_sm[0][rank * 32 + w * 4]),
                         s2u(&h_sm[1][rank * 32 + w * 4]),
                         s2u(&h_sm[2][rank * 32 + w * 4]) };

    const float4* prep = (const float4*)(g_pre + (size_t)dir * S_LEN * 1024) + m;
    float4 pre_cur = __ldg(&prep[0]);
    float* hs_out = g_hs + dir * HID2 + m;

    auto STEP = [&](int t, int b, int dowait, int parity) {
        int tn = (t + 1 < S_LEN) ? t + 1 : t;
        float4 pre_next = __ldg(&prep[(size_t)tn * 256]);
        if (dowait) WAIT_ACQ(mba[b], parity);
        ull a0 = 0, a1 = 0, a2 = 0, a3 = 0;
        const ull* hp = (const ull*)&h_sm[b][0];
#pragma unroll
        for (int q = 0; q < 16; q++) {
            ull h2 = hp[s + 8 * q];
            fma2(a0, wv[0][q], h2); fma2(a1, wv[1][q], h2);
            fma2(a2, wv[2][q], h2); fma2(a3, wv[3][q], h2);
        }
        float2 f0 = *(float2*)&a0, f1 = *(float2*)&a1, f2 = *(float2*)&a2, f3 = *(float2*)&a3;
        float s0 = f0.x + f0.y, s1 = f1.x + f1.y, s2 = f2.x + f2.y, s3 = f3.x + f3.y;
#pragma unroll
        for (int msk = 1; msk < 8; msk <<= 1) {
            s0 += __shfl_xor_sync(0xffffffffu, s0, msk);
            s1 += __shfl_xor_sync(0xffffffffu, s1, msk);
            s2 += __shfl_xor_sync(0xffffffffu, s2, msk);
            s3 += __shfl_xor_sync(0xffffffffu, s3, msk);
        }
        float gi = sigm(pre_cur.x + s0), gf = sigm(pre_cur.y + s1);
        float gg = tanh_(pre_cur.z + s2), go = sigm(pre_cur.w + s3);
        c = gf * c + gi * gg;
        float h = go * tanh_(c);

        int bn = (b + 1) % 3;
        float p0 = __shfl_sync(0xffffffffu, h, s);
        float p1 = __shfl_sync(0xffffffffu, h, s + 8);
        float p2 = __shfl_sync(0xffffffffu, h, s + 16);
        float p3 = __shfl_sync(0xffffffffu, h, s + 24);
        if (lane < 8) {
            unsigned da = mapa_(dsta[bn], (unsigned)lane);
            asm volatile("st.shared::cluster.v4.f32 [%0], {%1,%2,%3,%4};"
                         :: "r"(da), "f"(p0), "f"(p1), "f"(p2), "f"(p3) : "memory");
            unsigned ba = mapa_(mba[bn], (unsigned)lane);
            asm volatile("mbarrier.arrive.release.cluster.shared::cluster.b64 _, [%0];"
                         :: "r"(ba) : "memory");
        }
        if (s == 0) {
            int tpos = dir ? (S_LEN - 1 - t) : t;
            hs_out[(size_t)tpos * 512] = h;
        }
        pre_cur = pre_next;
    };

    STEP(0, 0, 0, 0);
    int par = 0;
    for (int t = 1; t < S_LEN - 1; t += 3) {
        STEP(t,     1, 1, par);
        STEP(t + 1, 2, 1, par);
        STEP(t + 2, 0, 1, par);
        par ^= 1;
    }
    STEP(S_LEN - 1, 1, 1, par);
    if (blockIdx.x == 0 && tid == 0) {
        long long dt = clock64() - t_start;
        printf("DIAG k_lstm8 cycles=%lld per_step=%lld\n", dt, dt / S_LEN);
    }
    cluster_sync_();
}

// ========================= K3: output projection ============================
__global__ __launch_bounds__(128) void k_feats(
    const float* __restrict__ w_out, const float* __restrict__ b_out)
{
    long long t_start = 0;
    if (blockIdx.x == 0 && threadIdx.x == 0) t_start = clock64();
    __shared__ float w_sm[NTAG * 516];
    const int tid = threadIdx.x;
    for (int idx = tid; idx < NTAG * 512; idx += 128)
        w_sm[(idx >> 9) * 516 + (idx & 511)] = __ldg(&w_out[idx]);
    __syncthreads();
    const int tl = tid >> 4, tag = tid & 15;
    const int t = blockIdx.x * 8 + tl;
    const float4* hp = (const float4*)(g_hs + (size_t)t * 512);
    const float4* wp = (const float4*)(w_sm + tag * 516);
    float acc = 0.0f;
#pragma unroll 4
    for (int k4 = 0; k4 < 128; k4++) {
        float4 h4 = hp[k4], w4 = wp[k4];
        acc += h4.x * w4.x + h4.y * w4.y + h4.z * w4.z + h4.w * w4.w;
    }
    g_feats[t * NTAG + tag] = acc + __ldg(&b_out[tag]);
    if (blockIdx.x == 0 && threadIdx.x == 0)
        printf("DIAG k_feats block0 cycles=%lld\n", clock64() - t_start);
}

// ========================= K4: Viterbi ======================================
__global__ __launch_bounds__(32) void k_vit(
    const float* __restrict__ trans, float* __restrict__ out, int out_size)
{
    long long t_start = 0;
    if (threadIdx.x == 0) t_start = clock64();
    __shared__ float fin_sm[NTAG];
    const int tid = threadIdx.x, j = tid & 15;
    float tr[NTAG];
#pragma unroll
    for (int i = 0; i < NTAG; i++) tr[i] = __ldg(&trans[j * NTAG + i]);

    float score = (j == 0) ? 0.0f : NEGV;
    float fcur = g_feats[j];
    for (int t = 0; t < S_LEN; t++) {
        float fnext = (t + 1 < S_LEN) ? g_feats[(t + 1) * NTAG + j] : 0.0f;
        float best = -3.4e38f; int bi = 0;
#pragma unroll
        for (int i = 0; i < NTAG; i++) {
            float si = __shfl_sync(0xffffffffu, score, i);
            float cand = si + tr[i];
            if (cand > best) { best = cand; bi = i; }
        }
        if (tid < NTAG) g_back[t * NTAG + j] = (unsigned char)bi;
        score = best + fcur;
        fcur = fnext;
    }
    if (tid < NTAG) fin_sm[j] = score + __ldg(&trans[1 * NTAG + j]);
    __syncwarp();
    if (tid == 0) {
        float bs = fin_sm[0]; int bl = 0;
#pragma unroll
        for (int i = 1; i < NTAG; i++) if (fin_sm[i] > bs) { bs = fin_sm[i]; bl = i; }
        const int off = (out_size > S_LEN) ? 1 : 0;
        if (off) out[0] = bs;
        int tag = bl;
#pragma unroll 4
        for (int t = S_LEN - 1; t > 0; t--) {
            out[off + t] = (float)tag;
            uint4 row = *(const uint4*)&g_back[t * NTAG];
            unsigned wsel = (tag & 8) ? ((tag & 4) ? row.w : row.z)
                                      : ((tag & 4) ? row.y : row.x);
            tag = (int)((wsel >> (8 * (tag & 3))) & 0xFu);
        }
        out[off] = (float)tag;
        printf("DIAG k_vit cycles=%lld\n", clock64() - t_start);
    }
}

extern "C" void kernel_launch(void* const* d_in, const int* in_sizes, int n_in,
                              void* d_out, int out_size)
{
    (void)in_sizes; (void)n_in;
    const int*   sent   = (const int*)  d_in[0];
    const float* emb    = (const float*)d_in[1];
    const float* w_ih_f = (const float*)d_in[2];
    const float* w_hh_f = (const float*)d_in[3];
    const float* b_f    = (const float*)d_in[4];
    const float* w_ih_b = (const float*)d_in[5];
    const float* w_hh_b = (const float*)d_in[6];
    const float* b_b    = (const float*)d_in[7];
    const float* h0_f   = (const float*)d_in[8];
    const float* c0_f   = (const float*)d_in[9];
    const float* h0_b   = (const float*)d_in[10];
    const float* c0_b   = (const float*)d_in[11];
    const float* w_out  = (const float*)d_in[12];
    const float* b_out  = (const float*)d_in[13];
    const float* trans  = (const float*)d_in[14];

    k_pre<<<dim3(512, 2), 256>>>(sent, emb, w_ih_f, b_f, w_ih_b, b_b);

    bool ok16 = false;
    cudaError_t e16 = cudaFuncSetAttribute((const void*)k_lstm16,
                         cudaFuncAttributeNonPortableClusterSizeAllowed, 1);
    {
        cudaLaunchConfig_t cfg = {};
        cfg.gridDim = dim3(32, 1, 1);
        cfg.blockDim = dim3(128, 1, 1);
        cfg.dynamicSmemBytes = 0;
        cfg.stream = 0;
        cudaLaunchAttribute at[1];
        at[0].id = cudaLaunchAttributeClusterDimension;
        at[0].val.clusterDim.x = 16;
        at[0].val.clusterDim.y = 1;
        at[0].val.clusterDim.z = 1;
        cfg.attrs = at;
        cfg.numAttrs = 1;
        cudaError_t el = cudaLaunchKernelEx(&cfg, k_lstm16,
                               w_hh_f, w_hh_b, h0_f, c0_f, h0_b, c0_b);
        if (el == cudaSuccess) ok16 = true;
        printf("DIAG host: setattr=%d launch16=%d -> %s\n",
               (int)e16, (int)el, ok16 ? "LSTM16" : "FALLBACK8");
        fflush(stdout);
    }
    if (!ok16)
        k_lstm8<<<16, 256>>>(w_hh_f, w_hh_b, h0_f, c0_f, h0_b, c0_b);

    k_feats<<<1024, 128>>>(w_out, b_out);
    k_vit<<<1, 32>>>(trans, (float*)d_out, out_size);
}